// round 9
// baseline (speedup 1.0000x reference)
#include <cuda_runtime.h>

#define BB 256
#define TT 512
#define DD 50
#define HH 128
#define G4 512
#define HID 256

typedef unsigned long long ull;

// ---- device scratch ----
__device__ float g_xgT[2][TT][G4][BB];   // input-gate preactivations [d][t][row][b]

__device__ __forceinline__ float sigf(float x)   { return 1.0f / (1.0f + __expf(-x)); }
__device__ __forceinline__ float tanhf_(float x) { return 2.0f / (1.0f + __expf(-2.0f * x)) - 1.0f; }

__device__ __forceinline__ ull pack2(float a, float b) {
    ull r; asm("mov.b64 %0,{%1,%2};" : "=l"(r) : "f"(a), "f"(b)); return r;
}
__device__ __forceinline__ void unpack2(ull v, float& a, float& b) {
    asm("mov.b64 {%0,%1},%2;" : "=f"(a), "=f"(b) : "l"(v));
}
__device__ __forceinline__ void fma2(ull a, ull b, ull& c) {
    asm("fma.rn.f32x2 %0,%1,%2,%0;" : "+l"(c) : "l"(a), "l"(b));
}
__device__ __forceinline__ ull add2(ull a, ull b) {
    ull r; asm("add.rn.f32x2 %0,%1,%2;" : "=l"(r) : "l"(a), "l"(b)); return r;
}
__device__ __forceinline__ unsigned smem_u32(const void* p) {
    unsigned r;
    asm("{ .reg .u64 t; cvta.to.shared.u64 t, %1; cvt.u32.u64 %0, t; }" : "=r"(r) : "l"(p));
    return r;
}
__device__ __forceinline__ void cp_async16(unsigned dst, const void* src) {
    asm volatile("cp.async.cg.shared.global [%0], [%1], 16;" :: "r"(dst), "l"(src) : "memory");
}

// ---------------------------------------------------------------------------
// Embedding lookup + input-gate GEMM -> transposed xg (unchanged)
// ---------------------------------------------------------------------------
__global__ void __launch_bounds__(256) embed_gemm(
    const int*   __restrict__ idx,
    const float* __restrict__ emb,
    const float* __restrict__ Wih_f, const float* __restrict__ bih_f, const float* __restrict__ bhh_f,
    const float* __restrict__ Wih_b, const float* __restrict__ bih_b, const float* __restrict__ bhh_b)
{
    __shared__ __align__(16) float xsA[16 * DD * 2];
    const int tid = threadIdx.x;
    const int b0  = blockIdx.x * 32;
    const int t   = blockIdx.y;

    for (int i = tid; i < 32 * DD; i += 256) {
        int b = i / DD, k = i - b * DD;
        int id = idx[(b0 + b) * TT + t];
        xsA[(b >> 1) * (2 * DD) + k * 2 + (b & 1)] = emb[id * DD + k];
    }
    __syncthreads();

    #pragma unroll 1
    for (int g = 0; g < 4; ++g) {
        int col = tid + g * 256;
        int dir = col >> 9;
        int n   = col & 511;
        const float* W = dir ? Wih_b : Wih_f;
        float bias = dir ? (bih_b[n] + bhh_b[n]) : (bih_f[n] + bhh_f[n]);

        float w[DD];
        #pragma unroll
        for (int k = 0; k < DD; ++k) w[k] = W[n * DD + k];

        ull acc[16];
        ull bp2 = pack2(bias, bias);
        #pragma unroll
        for (int p = 0; p < 16; ++p) acc[p] = bp2;

        #pragma unroll 2
        for (int k = 0; k < DD; ++k) {
            ull w2 = pack2(w[k], w[k]);
            #pragma unroll
            for (int p = 0; p < 16; ++p) {
                ull x = *(const ull*)&xsA[p * (2 * DD) + k * 2];
                fma2(x, w2, acc[p]);
            }
        }

        float* dst = &g_xgT[dir][t][n][b0];
        #pragma unroll
        for (int p = 0; p < 16; ++p) {
            float a, b; unpack2(acc[p], a, b);
            *(float2*)&dst[2 * p] = make_float2(a, b);
        }
    }
}

// ---------------------------------------------------------------------------
// Persistent LSTM recurrence: G=4 (all gates per thread), shfl reduction.
// grid (2 k-halves, 32 b-tiles of 8, 2 dirs) = 128 CTAs, cluster (2,1,1).
// 512 threads: kgrp = lane&7 (16-k input slice), kk = warp*4 + (lane>>3).
// Per k: 32B lane-distinct swizzled h read -> 16 FFMA2 (1 B/MAC).
// Partials over 8 kgrps reduced with 3-round shfl_xor butterfly (lane bits 0-2).
// ---------------------------------------------------------------------------
// h swizzle: float offset(k) = k*8 + ((k>>4)&7)*4  (conflict-free for lane=kgrp)
#define HBUF_F 1056

__global__ void __launch_bounds__(512, 1) __cluster_dims__(2, 1, 1)
lstm_g4(const float* __restrict__ Whh_f, const float* __restrict__ Whh_b,
        const float* __restrict__ masks, float* __restrict__ out)
{
    __shared__ __align__(16) float hb[2][HBUF_F];      // swizzled h, double-buffered
    __shared__ __align__(16) ull   gbuf[4 * 64 * 4];   // reduced gates [g][kk][bpair]
    __shared__ __align__(16) float xgb[2][4 * 64 * 8]; // xg staged [g][uk][b], dbl-buf

    const int tid  = threadIdx.x;
    const int rank = blockIdx.x;              // k-output half == cluster rank
    const int bt   = blockIdx.y;
    const int d    = blockIdx.z;
    const int K0   = rank * 64;
    const int bb0  = bt * 8;
    const int lane = tid & 31;
    const int warp = tid >> 5;

    // MAC role
    const int kgrp = lane & 7;                 // input k slice (16 k's)
    const int kk   = warp * 4 + (lane >> 3);   // k-output 0..63

    // Update role (tid < 256)
    const int uk = tid >> 2;
    const int bp = tid & 3;
    const int b0 = bb0 + 2 * bp;

    const float* Whh = d ? Whh_b : Whh_f;

    // ---- weights: 4 gate rows x 16 k in registers ----
    float w[4][16];
    #pragma unroll
    for (int g = 0; g < 4; ++g) {
        const float4* src = (const float4*)&Whh[(g * 128 + K0 + kk) * 128 + kgrp * 16];
        #pragma unroll
        for (int q = 0; q < 4; ++q) {
            float4 v = src[q];
            w[g][4 * q + 0] = v.x; w[g][4 * q + 1] = v.y;
            w[g][4 * q + 2] = v.z; w[g][4 * q + 3] = v.w;
        }
    }

    // zero h buffer 0
    for (int i = tid; i < HBUF_F; i += 512) hb[0][i] = 0.f;

    // h store offsets (update role): k = K0+uk, batches 2bp,2bp+1
    const int hk = K0 + uk;
    const unsigned hoff = (unsigned)((hk * 8 + ((hk >> 4) & 7) * 4 + bp * 2) * 4);
    unsigned rem0 = 0, rem1 = 0;
    float *loc0 = 0, *loc1 = 0;
    {
        unsigned a0 = smem_u32(&hb[0][0]) + hoff;
        unsigned a1 = smem_u32(&hb[1][0]) + hoff;
        unsigned pr = rank ^ 1;
        asm("mapa.shared::cluster.u32 %0, %1, %2;" : "=r"(rem0) : "r"(a0), "r"(pr));
        asm("mapa.shared::cluster.u32 %0, %1, %2;" : "=r"(rem1) : "r"(a1), "r"(pr));
        loc0 = (float*)((char*)&hb[0][0] + hoff);
        loc1 = (float*)((char*)&hb[1][0] + hoff);
    }

    // xg cp.async mapping: every thread copies one 16B chunk per step
    const int xgate = tid >> 7;                // 0..3
    const int xuk   = (tid & 127) >> 1;        // 0..63
    const int xhalf = tid & 1;                 // 0..1
    const unsigned xgdst[2] = {
        smem_u32(&xgb[0][0]) + (unsigned)((((xgate * 64 + xuk) * 8) + xhalf * 4) * 4),
        smem_u32(&xgb[1][0]) + (unsigned)((((xgate * 64 + xuk) * 8) + xhalf * 4) * 4)
    };
    const float* xsrc_base = &g_xgT[d][0][xgate * 128 + K0 + xuk][bb0 + xhalf * 4];

    // per-thread state (update role)
    float c0 = 0.f, c1 = 0.f;
    float m0 = -3.0e38f, m1 = -3.0e38f;

    const int tstep = d ? -1 : 1;
    int t = d ? (TT - 1) : 0;

    // stage step-0 xg
    cp_async16(xgdst[0], xsrc_base + (size_t)t * (G4 * BB));
    asm volatile("cp.async.commit_group;" ::: "memory");
    asm volatile("cp.async.wait_group 0;" ::: "memory");

    float pen0 = 0.f, pen1 = 0.f;
    if (tid < 256) {
        pen0 = (1.0f - __ldg(&masks[(b0)     * TT + t])) * 1e8f;
        pen1 = (1.0f - __ldg(&masks[(b0 + 1) * TT + t])) * 1e8f;
    }
    __syncthreads();

    int cur = 0;
    for (int s = 0; s < TT; ++s) {
        // stage next step's xg (completes during MAC loop)
        int t2 = t + tstep;
        t2 = (t2 < 0) ? 0 : (t2 > TT - 1 ? TT - 1 : t2);
        cp_async16(xgdst[(s + 1) & 1], xsrc_base + (size_t)t2 * (G4 * BB));
        asm volatile("cp.async.commit_group;" ::: "memory");

        float npen0 = pen0, npen1 = pen1;
        if (tid < 256) {
            pen0 = (1.0f - __ldg(&masks[(b0)     * TT + t2])) * 1e8f;
            pen1 = (1.0f - __ldg(&masks[(b0 + 1) * TT + t2])) * 1e8f;
        }

        // ---- MAC: acc[4 gates][4 bpairs] over own 16-k slice ----
        ull acc[4][4];
        #pragma unroll
        for (int g = 0; g < 4; ++g)
            #pragma unroll
            for (int p = 0; p < 4; ++p) acc[g][p] = 0ull;

        const float* hp = &hb[cur][kgrp * 132];
        #pragma unroll
        for (int ki = 0; ki < 16; ++ki) {
            ulonglong2 A = *(const ulonglong2*)(hp + ki * 8);      // b0..3
            ulonglong2 B = *(const ulonglong2*)(hp + ki * 8 + 4);  // b4..7
            #pragma unroll
            for (int g = 0; g < 4; ++g) {
                ull w2 = pack2(w[g][ki], w[g][ki]);
                fma2(A.x, w2, acc[g][0]);
                fma2(A.y, w2, acc[g][1]);
                fma2(B.x, w2, acc[g][2]);
                fma2(B.y, w2, acc[g][3]);
            }
        }

        // ---- butterfly reduce over kgrp (lane bits 0-2) ----
        #pragma unroll
        for (int m = 1; m < 8; m <<= 1) {
            #pragma unroll
            for (int g = 0; g < 4; ++g)
                #pragma unroll
                for (int p = 0; p < 4; ++p)
                    acc[g][p] = add2(acc[g][p],
                                     __shfl_xor_sync(0xffffffffu, acc[g][p], m));
        }
        if (kgrp == 0) {
            #pragma unroll
            for (int g = 0; g < 4; ++g)
                #pragma unroll
                for (int p = 0; p < 4; ++p)
                    gbuf[(g * 64 + kk) * 4 + p] = acc[g][p];
        }

        // current step's xg must be resident (allow the just-issued group)
        asm volatile("cp.async.wait_group 1;" ::: "memory");
        __syncthreads();

        // ---- update role: gates + xg -> c,h, masked max, h push ----
        if (tid < 256) {
            const ull* xg = (const ull*)&xgb[s & 1][0];
            ull gi = add2(gbuf[(0 * 64 + uk) * 4 + bp], xg[(0 * 64 + uk) * 4 + bp]);
            ull gf = add2(gbuf[(1 * 64 + uk) * 4 + bp], xg[(1 * 64 + uk) * 4 + bp]);
            ull gg = add2(gbuf[(2 * 64 + uk) * 4 + bp], xg[(2 * 64 + uk) * 4 + bp]);
            ull go = add2(gbuf[(3 * 64 + uk) * 4 + bp], xg[(3 * 64 + uk) * 4 + bp]);

            float gix, giy, gfx, gfy, ggx, ggy, gox, goy;
            unpack2(gi, gix, giy); unpack2(gf, gfx, gfy);
            unpack2(gg, ggx, ggy); unpack2(go, gox, goy);

            c0 = sigf(gfx) * c0 + sigf(gix) * tanhf_(ggx);
            float hv0 = sigf(gox) * tanhf_(c0);
            m0 = fmaxf(m0, hv0 - npen0);

            c1 = sigf(gfy) * c1 + sigf(giy) * tanhf_(ggy);
            float hv1 = sigf(goy) * tanhf_(c1);
            m1 = fmaxf(m1, hv1 - npen1);

            if (s < TT - 1) {
                if (cur) { *(float2*)loc0 = make_float2(hv0, hv1); }
                else     { *(float2*)loc1 = make_float2(hv0, hv1); }
                unsigned ra = cur ? rem0 : rem1;
                asm volatile("st.shared::cluster.v2.f32 [%0], {%1,%2};"
                             :: "r"(ra), "f"(hv0), "f"(hv1) : "memory");
            }
        }

        if (s < TT - 1) {
            // cluster barrier: orders DSMEM pushes + gbuf/hbuf reuse, syncs CTAs
            asm volatile("barrier.cluster.arrive.aligned;" ::: "memory");
            asm volatile("barrier.cluster.wait.aligned;"   ::: "memory");
        }

        cur ^= 1;
        t += tstep;
    }

    if (tid < 256) {
        out[(b0)     * HID + d * HH + K0 + uk] = m0;
        out[(b0 + 1) * HID + d * HH + K0 + uk] = m1;
    }
}

// ---------------------------------------------------------------------------
extern "C" void kernel_launch(void* const* d_in, const int* in_sizes, int n_in,
                              void* d_out, int out_size)
{
    (void)in_sizes; (void)n_in; (void)out_size;
    const int*   idx   = (const int*)  d_in[0];
    const float* masks = (const float*)d_in[1];
    const float* emb   = (const float*)d_in[2];
    const float* Wih_f = (const float*)d_in[3];
    const float* Whh_f = (const float*)d_in[4];
    const float* bih_f = (const float*)d_in[5];
    const float* bhh_f = (const float*)d_in[6];
    const float* Wih_b = (const float*)d_in[7];
    const float* Whh_b = (const float*)d_in[8];
    const float* bih_b = (const float*)d_in[9];
    const float* bhh_b = (const float*)d_in[10];
    float* out = (float*)d_out;

    embed_gemm<<<dim3(8, TT), 256>>>(idx, emb, Wih_f, bih_f, bhh_f,
                                     Wih_b, bih_b, bhh_b);
    lstm_g4<<<dim3(2, 32, 2), 512>>>(Whh_f, Whh_b, masks, out);
}

// round 11
// speedup vs baseline: 1.0215x; 1.0215x over previous
#include <cuda_runtime.h>

#define BB 256
#define TT 512
#define DD 50
#define HH 128
#define G4 512
#define HID 256

typedef unsigned long long ull;

// ---- device scratch ----
__device__ float g_xgT[2][TT][G4][BB];   // input-gate preactivations [d][t][row][b]

__device__ __forceinline__ float sigf(float x)   { return 1.0f / (1.0f + __expf(-x)); }
__device__ __forceinline__ float tanhf_(float x) { return 2.0f / (1.0f + __expf(-2.0f * x)) - 1.0f; }

__device__ __forceinline__ ull pack2(float a, float b) {
    ull r; asm("mov.b64 %0,{%1,%2};" : "=l"(r) : "f"(a), "f"(b)); return r;
}
__device__ __forceinline__ void unpack2(ull v, float& a, float& b) {
    asm("mov.b64 {%0,%1},%2;" : "=f"(a), "=f"(b) : "l"(v));
}
__device__ __forceinline__ void fma2(ull a, ull b, ull& c) {
    asm("fma.rn.f32x2 %0,%1,%2,%0;" : "+l"(c) : "l"(a), "l"(b));
}
__device__ __forceinline__ ull add2(ull a, ull b) {
    ull r; asm("add.rn.f32x2 %0,%1,%2;" : "=l"(r) : "l"(a), "l"(b)); return r;
}
__device__ __forceinline__ unsigned smem_u32(const void* p) {
    unsigned r;
    asm("{ .reg .u64 t; cvta.to.shared.u64 t, %1; cvt.u32.u64 %0, t; }" : "=r"(r) : "l"(p));
    return r;
}

// ---------------------------------------------------------------------------
// Embedding lookup + input-gate GEMM -> transposed xg (unchanged)
// ---------------------------------------------------------------------------
__global__ void __launch_bounds__(256) embed_gemm(
    const int*   __restrict__ idx,
    const float* __restrict__ emb,
    const float* __restrict__ Wih_f, const float* __restrict__ bih_f, const float* __restrict__ bhh_f,
    const float* __restrict__ Wih_b, const float* __restrict__ bih_b, const float* __restrict__ bhh_b)
{
    __shared__ __align__(16) float xsA[16 * DD * 2];
    const int tid = threadIdx.x;
    const int b0  = blockIdx.x * 32;
    const int t   = blockIdx.y;

    for (int i = tid; i < 32 * DD; i += 256) {
        int b = i / DD, k = i - b * DD;
        int id = idx[(b0 + b) * TT + t];
        xsA[(b >> 1) * (2 * DD) + k * 2 + (b & 1)] = emb[id * DD + k];
    }
    __syncthreads();

    #pragma unroll 1
    for (int g = 0; g < 4; ++g) {
        int col = tid + g * 256;
        int dir = col >> 9;
        int n   = col & 511;
        const float* W = dir ? Wih_b : Wih_f;
        float bias = dir ? (bih_b[n] + bhh_b[n]) : (bih_f[n] + bhh_f[n]);

        float w[DD];
        #pragma unroll
        for (int k = 0; k < DD; ++k) w[k] = W[n * DD + k];

        ull acc[16];
        ull bp2 = pack2(bias, bias);
        #pragma unroll
        for (int p = 0; p < 16; ++p) acc[p] = bp2;

        #pragma unroll 2
        for (int k = 0; k < DD; ++k) {
            ull w2 = pack2(w[k], w[k]);
            #pragma unroll
            for (int p = 0; p < 16; ++p) {
                ull x = *(const ull*)&xsA[p * (2 * DD) + k * 2];
                fma2(x, w2, acc[p]);
            }
        }

        float* dst = &g_xgT[dir][t][n][b0];
        #pragma unroll
        for (int p = 0; p < 16; ++p) {
            float a, b; unpack2(acc[p], a, b);
            *(float2*)&dst[2 * p] = make_float2(a, b);
        }
    }
}

// ---------------------------------------------------------------------------
// Persistent LSTM recurrence: k-quarter CTAs, 2 CTAs/SM, 4-CTA clusters.
// grid (4 kq, 32 bt, 2 dir) = 256 CTAs x 256 threads, cluster (4,1,1).
// CTA: 32 k-outputs x 4 gates x 8 batches, weights 64KB in smem.
// lane = bp(2b) | kkl(2b) | kgrp(1b): per k-iter/warp 1 LDS.128(w) + 1 LDS.64(h),
// bank-disjoint via half-pads. 1-round shfl reduce; every lane updates one (k,b).
// ---------------------------------------------------------------------------
// dyn smem: [0, 65600)       weights: [kin 128][kk 32][4 g] + 64B pad at kin=64
//           [65600, 69728)   hb0: h [kin 128][b 8] + 32B pad at kin=64
//           [69728, 73856)   hb1
#define WSM_PAD_F   16          // 64B in floats
#define HB_PAD_F    8           // 32B in floats
#define HB0_OFF     65600
#define HB1_OFF     69728
#define SMEM_BYTES  73856

__global__ void __launch_bounds__(256, 2) __cluster_dims__(4, 1, 1)
lstm_quad(const float* __restrict__ Whh_f, const float* __restrict__ Whh_b,
          const float* __restrict__ masks, float* __restrict__ out)
{
    extern __shared__ __align__(16) char smem[];
    float* wsm = (float*)smem;
    float* hb0 = (float*)(smem + HB0_OFF);

    const int tid  = threadIdx.x;
    const int kq   = blockIdx.x;            // k-quarter == cluster rank
    const int bt   = blockIdx.y;
    const int d    = blockIdx.z;
    const int K0   = kq * 32;
    const int bb0  = bt * 8;
    const int lane = tid & 31;
    const int warp = tid >> 5;

    const int bp    = lane & 3;             // batch pair
    const int kkl   = (lane >> 2) & 3;
    const int kgrp  = lane >> 4;            // k-input half
    const int kk    = warp * 4 + kkl;       // 0..31 (k-output within quarter)
    const int kglob = K0 + kk;
    const int bu    = bb0 + 2 * bp + kgrp;  // owned batch for update

    const float* Whh = d ? Whh_b : Whh_f;

    // ---- stage weights: wsm[kin][kk][4] with 64B pad at kin>=64 ----
    for (int i = tid; i < 4096; i += 256) {
        int kk2 = i & 31, kin = i >> 5;
        int base = kin * 128 + (kin >= 64 ? WSM_PAD_F : 0) + kk2 * 4;
        int row = K0 + kk2;
        wsm[base + 0] = Whh[(0 * 128 + row) * 128 + kin];
        wsm[base + 1] = Whh[(1 * 128 + row) * 128 + kin];
        wsm[base + 2] = Whh[(2 * 128 + row) * 128 + kin];
        wsm[base + 3] = Whh[(3 * 128 + row) * 128 + kin];
    }
    // zero hb0 (1032 floats)
    for (int i = tid; i < 1032; i += 256) hb0[i] = 0.f;

    // ---- per-thread MAC pointers ----
    const float* wp = wsm + kgrp * (64 * 128 + WSM_PAD_F) + kk * 4;   // +i*128/iter
    const int hrd = kgrp * (64 * 8 + HB_PAD_F) + bp * 2;              // +i*8/iter

    // ---- h store offset (update role) + peer addresses ----
    const unsigned hoff_b = (unsigned)((kglob * 8 + (kq >= 2 ? HB_PAD_F : 0)
                                        + 2 * bp + kgrp) * 4);
    float* loc0 = (float*)(smem + HB0_OFF + hoff_b);
    float* loc1 = (float*)(smem + HB1_OFF + hoff_b);
    unsigned rem0[3], rem1[3];
    {
        unsigned a0 = smem_u32(smem + HB0_OFF) + hoff_b;
        unsigned a1 = smem_u32(smem + HB1_OFF) + hoff_b;
        #pragma unroll
        for (int p = 0; p < 3; ++p) {
            unsigned pr = (kq + 1 + p) & 3;
            asm("mapa.shared::cluster.u32 %0, %1, %2;" : "=r"(rem0[p]) : "r"(a0), "r"(pr));
            asm("mapa.shared::cluster.u32 %0, %1, %2;" : "=r"(rem1[p]) : "r"(a1), "r"(pr));
        }
    }

    // ---- per-thread state ----
    float c = 0.f, m = -3.0e38f;

    const int tstep = d ? -1 : 1;
    int t = d ? (TT - 1) : 0;

    // prefetch xg (4 gate rows, own batch) + mask penalty for step 0
    float xn0, xn1, xn2, xn3, pen;
    {
        const float* p = &g_xgT[d][t][0][bu];
        xn0 = __ldg(p + (0 * 128 + kglob) * BB);
        xn1 = __ldg(p + (1 * 128 + kglob) * BB);
        xn2 = __ldg(p + (2 * 128 + kglob) * BB);
        xn3 = __ldg(p + (3 * 128 + kglob) * BB);
        pen = (1.0f - __ldg(&masks[bu * TT + t])) * 1e8f;
    }

    __syncthreads();   // weights + hb0 ready (local); peers independent

    int cur = 0;
    for (int s = 0; s < TT; ++s) {
        float cx0 = xn0, cx1 = xn1, cx2 = xn2, cx3 = xn3, cpen = pen;
        // prefetch next step
        {
            int t2 = t + tstep;
            t2 = (t2 < 0) ? 0 : (t2 > TT - 1 ? TT - 1 : t2);
            const float* p = &g_xgT[d][t2][0][bu];
            xn0 = __ldg(p + (0 * 128 + kglob) * BB);
            xn1 = __ldg(p + (1 * 128 + kglob) * BB);
            xn2 = __ldg(p + (2 * 128 + kglob) * BB);
            xn3 = __ldg(p + (3 * 128 + kglob) * BB);
            pen = (1.0f - __ldg(&masks[bu * TT + t2])) * 1e8f;
        }

        // ---- MAC: 64 own-k-half iters; acc (i,f)/(g,o) x 2 batches ----
        ull aifA = 0, aifB = 0, agoA = 0, agoB = 0;
        const float* hc = (cur ? (float*)(smem + HB1_OFF) : (float*)(smem + HB0_OFF)) + hrd;
        #pragma unroll
        for (int i = 0; i < 64; ++i) {
            ulonglong2 wu = *(const ulonglong2*)(wp + i * 128);  // (wi,wf),(wg,wo)
            float2     hv = *(const float2*)(hc + i * 8);        // h[k][bA], h[k][bB]
            ull hA = pack2(hv.x, hv.x);
            ull hB = pack2(hv.y, hv.y);
            fma2(hA, wu.x, aifA);
            fma2(hB, wu.x, aifB);
            fma2(hA, wu.y, agoA);
            fma2(hB, wu.y, agoB);
        }

        // ---- single-round reduce across kgrp (lane bit 4) ----
        aifA = add2(aifA, __shfl_xor_sync(0xffffffffu, aifA, 16));
        aifB = add2(aifB, __shfl_xor_sync(0xffffffffu, aifB, 16));
        agoA = add2(agoA, __shfl_xor_sync(0xffffffffu, agoA, 16));
        agoB = add2(agoB, __shfl_xor_sync(0xffffffffu, agoB, 16));

        // ---- update: every lane owns (kglob, bu) — batch selected by kgrp ----
        ull aif = kgrp ? aifB : aifA;
        ull ago = kgrp ? agoB : agoA;
        float gi, gf, gg, go;
        unpack2(aif, gi, gf);
        unpack2(ago, gg, go);
        gi += cx0; gf += cx1; gg += cx2; go += cx3;

        c = sigf(gf) * c + sigf(gi) * tanhf_(gg);
        float hv = sigf(go) * tanhf_(c);
        m = fmaxf(m, hv - cpen);

        if (s < TT - 1) {
            // write next h buffer: local + 3 DSMEM peers (4B each)
            if (cur) { *loc0 = hv; } else { *loc1 = hv; }
            const unsigned* rr = cur ? rem0 : rem1;
            asm volatile("st.shared::cluster.f32 [%0], %1;" :: "r"(rr[0]), "f"(hv) : "memory");
            asm volatile("st.shared::cluster.f32 [%0], %1;" :: "r"(rr[1]), "f"(hv) : "memory");
            asm volatile("st.shared::cluster.f32 [%0], %1;" :: "r"(rr[2]), "f"(hv) : "memory");
            // 4-CTA split cluster barrier: orders pushes + hb reuse
            asm volatile("barrier.cluster.arrive.aligned;" ::: "memory");
            asm volatile("barrier.cluster.wait.aligned;"   ::: "memory");
        }

        cur ^= 1;
        t += tstep;
    }

    out[bu * HID + d * HH + kglob] = m;
}

// ---------------------------------------------------------------------------
extern "C" void kernel_launch(void* const* d_in, const int* in_sizes, int n_in,
                              void* d_out, int out_size)
{
    (void)in_sizes; (void)n_in; (void)out_size;
    const int*   idx   = (const int*)  d_in[0];
    const float* masks = (const float*)d_in[1];
    const float* emb   = (const float*)d_in[2];
    const float* Wih_f = (const float*)d_in[3];
    const float* Whh_f = (const float*)d_in[4];
    const float* bih_f = (const float*)d_in[5];
    const float* bhh_f = (const float*)d_in[6];
    const float* Wih_b = (const float*)d_in[7];
    const float* Whh_b = (const float*)d_in[8];
    const float* bih_b = (const float*)d_in[9];
    const float* bhh_b = (const float*)d_in[10];
    float* out = (float*)d_out;

    // idempotent, capture-legal; no static state per harness rules
    cudaFuncSetAttribute(lstm_quad,
                         cudaFuncAttributeMaxDynamicSharedMemorySize, SMEM_BYTES);

    embed_gemm<<<dim3(8, TT), 256>>>(idx, emb, Wih_f, bih_f, bhh_f,
                                     Wih_b, bih_b, bhh_b);
    lstm_quad<<<dim3(4, 32, 2), 256, SMEM_BYTES>>>(Whh_f, Whh_b, masks, out);
}

// round 12
// speedup vs baseline: 1.2112x; 1.1857x over previous
#include <cuda_runtime.h>

#define BB 256
#define TT 512
#define DD 50
#define HH 128
#define G4 512
#define HID 256

typedef unsigned long long ull;

// ---- device scratch ----
__device__ float g_xgT[2][TT][G4][BB];   // input-gate preactivations [d][t][row][b]

__device__ __forceinline__ float sigf(float x)   { return 1.0f / (1.0f + __expf(-x)); }
__device__ __forceinline__ float tanhf_(float x) { return 2.0f / (1.0f + __expf(-2.0f * x)) - 1.0f; }

__device__ __forceinline__ ull pack2(float a, float b) {
    ull r; asm("mov.b64 %0,{%1,%2};" : "=l"(r) : "f"(a), "f"(b)); return r;
}
__device__ __forceinline__ void unpack2(ull v, float& a, float& b) {
    asm("mov.b64 {%0,%1},%2;" : "=f"(a), "=f"(b) : "l"(v));
}
__device__ __forceinline__ void fma2(ull a, ull b, ull& c) {
    asm("fma.rn.f32x2 %0,%1,%2,%0;" : "+l"(c) : "l"(a), "l"(b));
}
__device__ __forceinline__ ull add2(ull a, ull b) {
    ull r; asm("add.rn.f32x2 %0,%1,%2;" : "=l"(r) : "l"(a), "l"(b)); return r;
}
__device__ __forceinline__ unsigned smem_u32(const void* p) {
    unsigned r;
    asm("{ .reg .u64 t; cvta.to.shared.u64 t, %1; cvt.u32.u64 %0, t; }" : "=r"(r) : "l"(p));
    return r;
}

// ---------------------------------------------------------------------------
// Embedding lookup + input-gate GEMM -> transposed xg (unchanged)
// ---------------------------------------------------------------------------
__global__ void __launch_bounds__(256) embed_gemm(
    const int*   __restrict__ idx,
    const float* __restrict__ emb,
    const float* __restrict__ Wih_f, const float* __restrict__ bih_f, const float* __restrict__ bhh_f,
    const float* __restrict__ Wih_b, const float* __restrict__ bih_b, const float* __restrict__ bhh_b)
{
    __shared__ __align__(16) float xsA[16 * DD * 2];
    const int tid = threadIdx.x;
    const int b0  = blockIdx.x * 32;
    const int t   = blockIdx.y;

    for (int i = tid; i < 32 * DD; i += 256) {
        int b = i / DD, k = i - b * DD;
        int id = idx[(b0 + b) * TT + t];
        xsA[(b >> 1) * (2 * DD) + k * 2 + (b & 1)] = emb[id * DD + k];
    }
    __syncthreads();

    #pragma unroll 1
    for (int g = 0; g < 4; ++g) {
        int col = tid + g * 256;
        int dir = col >> 9;
        int n   = col & 511;
        const float* W = dir ? Wih_b : Wih_f;
        float bias = dir ? (bih_b[n] + bhh_b[n]) : (bih_f[n] + bhh_f[n]);

        float w[DD];
        #pragma unroll
        for (int k = 0; k < DD; ++k) w[k] = W[n * DD + k];

        ull acc[16];
        ull bp2 = pack2(bias, bias);
        #pragma unroll
        for (int p = 0; p < 16; ++p) acc[p] = bp2;

        #pragma unroll 2
        for (int k = 0; k < DD; ++k) {
            ull w2 = pack2(w[k], w[k]);
            #pragma unroll
            for (int p = 0; p < 16; ++p) {
                ull x = *(const ull*)&xsA[p * (2 * DD) + k * 2];
                fma2(x, w2, acc[p]);
            }
        }

        float* dst = &g_xgT[dir][t][n][b0];
        #pragma unroll
        for (int p = 0; p < 16; ++p) {
            float a, b; unpack2(acc[p], a, b);
            *(float2*)&dst[2 * p] = make_float2(a, b);
        }
    }
}

// ---------------------------------------------------------------------------
// Persistent LSTM recurrence: weights in regs (no replication), h at 1 B/MAC,
// shfl reduction, no smem gate exchange, no __syncthreads in loop.
// grid (4 kq, 32 bt, 2 dir) = 256 CTAs x 256 threads, cluster (4,1,1), 2 CTA/SM.
// Thread: kk = warp*4 + (lane&3) k-output, kgrp = lane>>2 -> 16-k input slice;
// owns all 4 gates x 8 batches over its slice (64 w regs, 16 ull accs).
// h layout: 132-word section per kgrp -> 8 kgrps hit disjoint bank quads,
// 4 kkl lanes broadcast => conflict-free LDS.128.
// Reduce: 2 full shfl_xor rounds (16,8) + 1 selective round (4) on own bpair.
// Update lane owns (kk, b=kgrp): c/h in regs, 4B DSMEM push x3, cluster barrier.
// ---------------------------------------------------------------------------
#define SEC_W  132                 // words per 16-k section (16*8 + 4 pad)
#define HB_W   (8 * SEC_W)         // 1056 words per buffer

__global__ void __launch_bounds__(256, 2) __cluster_dims__(4, 1, 1)
lstm_rw(const float* __restrict__ Whh_f, const float* __restrict__ Whh_b,
        const float* __restrict__ masks, float* __restrict__ out)
{
    __shared__ __align__(16) float hb[2][HB_W];

    const int tid  = threadIdx.x;
    const int kq   = blockIdx.x;             // k-quarter == cluster rank
    const int bt   = blockIdx.y;
    const int d    = blockIdx.z;
    const int K0   = kq * 32;
    const int bb0  = bt * 8;
    const int lane = tid & 31;
    const int warp = tid >> 5;

    const int kkl   = lane & 3;
    const int kgrp  = lane >> 2;             // 0..7 (lane bits 2..4 -> xor 4,8,16)
    const int kk    = warp * 4 + kkl;        // 0..31
    const int kglob = K0 + kk;
    const int bu    = bb0 + kgrp;            // owned batch

    const float* Whh = d ? Whh_b : Whh_f;

    // ---- weights: 4 gate rows x own 16-k slice, in registers ----
    float w[4][16];
    #pragma unroll
    for (int g = 0; g < 4; ++g) {
        const float4* src = (const float4*)&Whh[(g * 128 + kglob) * 128 + kgrp * 16];
        #pragma unroll
        for (int q = 0; q < 4; ++q) {
            float4 v = src[q];
            w[g][4 * q + 0] = v.x; w[g][4 * q + 1] = v.y;
            w[g][4 * q + 2] = v.z; w[g][4 * q + 3] = v.w;
        }
    }

    // zero h buffer 0
    for (int i = tid; i < HB_W; i += 256) hb[0][i] = 0.f;

    // ---- h store word + peer push addresses ----
    const int hw = (kglob >> 4) * SEC_W + (kglob & 15) * 8 + kgrp;
    float* loc0 = &hb[0][hw];
    const unsigned par_off = (unsigned)(HB_W * 4);   // hb[1] - hb[0] bytes
    unsigned rem0[3];
    {
        unsigned a0 = smem_u32(&hb[0][0]) + (unsigned)(hw * 4);
        #pragma unroll
        for (int p = 0; p < 3; ++p) {
            unsigned pr = (kq + 1 + p) & 3;
            asm("mapa.shared::cluster.u32 %0, %1, %2;" : "=r"(rem0[p]) : "r"(a0), "r"(pr));
        }
    }

    // ---- per-thread state ----
    float c = 0.f, m = -3.0e38f;

    const int tstep = d ? -1 : 1;
    int t = d ? (TT - 1) : 0;

    // prefetch xg (4 gate rows, own batch) + mask penalty for step 0
    float xn0, xn1, xn2, xn3, pen;
    {
        const float* p = &g_xgT[d][t][0][bu];
        xn0 = __ldg(p + (0 * 128 + kglob) * BB);
        xn1 = __ldg(p + (1 * 128 + kglob) * BB);
        xn2 = __ldg(p + (2 * 128 + kglob) * BB);
        xn3 = __ldg(p + (3 * 128 + kglob) * BB);
        pen = (1.0f - __ldg(&masks[bu * TT + t])) * 1e8f;
    }

    __syncthreads();   // hb[0] zeroed (local); peers independent

    const int mybp = kgrp >> 1;
    const int hie  = kgrp & 1;

    int cur = 0;
    for (int s = 0; s < TT; ++s) {
        float cx0 = xn0, cx1 = xn1, cx2 = xn2, cx3 = xn3, cpen = pen;
        // prefetch next step (hides under MAC loop)
        {
            int t2 = t + tstep;
            t2 = (t2 < 0) ? 0 : (t2 > TT - 1 ? TT - 1 : t2);
            const float* p = &g_xgT[d][t2][0][bu];
            xn0 = __ldg(p + (0 * 128 + kglob) * BB);
            xn1 = __ldg(p + (1 * 128 + kglob) * BB);
            xn2 = __ldg(p + (2 * 128 + kglob) * BB);
            xn3 = __ldg(p + (3 * 128 + kglob) * BB);
            pen = (1.0f - __ldg(&masks[bu * TT + t2])) * 1e8f;
        }

        // ---- MAC: own 16-k slice, 4 gates x 4 batch-pairs ----
        ull A[4][4];
        #pragma unroll
        for (int g = 0; g < 4; ++g)
            #pragma unroll
            for (int p = 0; p < 4; ++p) A[g][p] = 0ull;

        const float* hc = &hb[cur][kgrp * SEC_W];
        #pragma unroll
        for (int i = 0; i < 16; ++i) {
            ulonglong2 h03 = *(const ulonglong2*)(hc + i * 8);      // b0b1, b2b3
            ulonglong2 h47 = *(const ulonglong2*)(hc + i * 8 + 4);  // b4b5, b6b7
            #pragma unroll
            for (int g = 0; g < 4; ++g) {
                ull w2 = pack2(w[g][i], w[g][i]);
                fma2(h03.x, w2, A[g][0]);
                fma2(h03.y, w2, A[g][1]);
                fma2(h47.x, w2, A[g][2]);
                fma2(h47.y, w2, A[g][3]);
            }
        }

        // ---- reduce over 8 kgrps: 2 full rounds + 1 selective ----
        #pragma unroll
        for (int g = 0; g < 4; ++g)
            #pragma unroll
            for (int p = 0; p < 4; ++p) {
                A[g][p] = add2(A[g][p], __shfl_xor_sync(0xffffffffu, A[g][p], 16));
                A[g][p] = add2(A[g][p], __shfl_xor_sync(0xffffffffu, A[g][p], 8));
            }
        ull tg[4];
        #pragma unroll
        for (int g = 0; g < 4; ++g) {
            ull v = (mybp & 2) ? ((mybp & 1) ? A[g][3] : A[g][2])
                               : ((mybp & 1) ? A[g][1] : A[g][0]);
            tg[g] = add2(v, __shfl_xor_sync(0xffffffffu, v, 4));
        }

        // ---- update: lane owns (kglob, bu) ----
        float aa, bb2, gi, gf, gg, go;
        unpack2(tg[0], aa, bb2); gi = hie ? bb2 : aa;
        unpack2(tg[1], aa, bb2); gf = hie ? bb2 : aa;
        unpack2(tg[2], aa, bb2); gg = hie ? bb2 : aa;
        unpack2(tg[3], aa, bb2); go = hie ? bb2 : aa;
        gi += cx0; gf += cx1; gg += cx2; go += cx3;

        c = sigf(gf) * c + sigf(gi) * tanhf_(gg);
        float hv = sigf(go) * tanhf_(c);
        m = fmaxf(m, hv - cpen);

        if (s < TT - 1) {
            // write next h buffer: local + 3 DSMEM peers (4B each)
            unsigned nb = cur ? 0u : par_off;
            *(float*)((char*)loc0 + nb) = hv;
            asm volatile("st.shared::cluster.f32 [%0], %1;" :: "r"(rem0[0] + nb), "f"(hv) : "memory");
            asm volatile("st.shared::cluster.f32 [%0], %1;" :: "r"(rem0[1] + nb), "f"(hv) : "memory");
            asm volatile("st.shared::cluster.f32 [%0], %1;" :: "r"(rem0[2] + nb), "f"(hv) : "memory");
            // split cluster barrier: orders pushes + hb reuse, syncs CTAs
            asm volatile("barrier.cluster.arrive.aligned;" ::: "memory");
            asm volatile("barrier.cluster.wait.aligned;"   ::: "memory");
        }

        cur ^= 1;
        t += tstep;
    }

    out[bu * HID + d * HH + kglob] = m;
}

// ---------------------------------------------------------------------------
extern "C" void kernel_launch(void* const* d_in, const int* in_sizes, int n_in,
                              void* d_out, int out_size)
{
    (void)in_sizes; (void)n_in; (void)out_size;
    const int*   idx   = (const int*)  d_in[0];
    const float* masks = (const float*)d_in[1];
    const float* emb   = (const float*)d_in[2];
    const float* Wih_f = (const float*)d_in[3];
    const float* Whh_f = (const float*)d_in[4];
    const float* bih_f = (const float*)d_in[5];
    const float* bhh_f = (const float*)d_in[6];
    const float* Wih_b = (const float*)d_in[7];
    const float* Whh_b = (const float*)d_in[8];
    const float* bih_b = (const float*)d_in[9];
    const float* bhh_b = (const float*)d_in[10];
    float* out = (float*)d_out;

    embed_gemm<<<dim3(8, TT), 256>>>(idx, emb, Wih_f, bih_f, bhh_f,
                                     Wih_b, bih_b, bhh_b);
    lstm_rw<<<dim3(4, 32, 2), 256>>>(Whh_f, Whh_b, masks, out);
}

// round 13
// speedup vs baseline: 1.2877x; 1.0632x over previous
#include <cuda_runtime.h>

#define BB 256
#define TT 512
#define DD 50
#define HH 128
#define G4 512
#define HID 256

typedef unsigned long long ull;

// ---- device scratch ----
__device__ float g_xgT[2][TT][G4][BB];   // input-gate preactivations [d][t][row][b]

__device__ __forceinline__ float sigf(float x)   { return 1.0f / (1.0f + __expf(-x)); }
__device__ __forceinline__ float tanhf_(float x) { return 2.0f / (1.0f + __expf(-2.0f * x)) - 1.0f; }

__device__ __forceinline__ ull pack2(float a, float b) {
    ull r; asm("mov.b64 %0,{%1,%2};" : "=l"(r) : "f"(a), "f"(b)); return r;
}
__device__ __forceinline__ void unpack2(ull v, float& a, float& b) {
    asm("mov.b64 {%0,%1},%2;" : "=f"(a), "=f"(b) : "l"(v));
}
__device__ __forceinline__ void fma2(ull a, ull b, ull& c) {
    asm("fma.rn.f32x2 %0,%1,%2,%0;" : "+l"(c) : "l"(a), "l"(b));
}
__device__ __forceinline__ ull add2(ull a, ull b) {
    ull r; asm("add.rn.f32x2 %0,%1,%2;" : "=l"(r) : "l"(a), "l"(b)); return r;
}
__device__ __forceinline__ unsigned smem_u32(const void* p) {
    unsigned r;
    asm("{ .reg .u64 t; cvta.to.shared.u64 t, %1; cvt.u32.u64 %0, t; }" : "=r"(r) : "l"(p));
    return r;
}

// ---------------------------------------------------------------------------
// Embedding lookup + input-gate GEMM -> transposed xg (unchanged)
// ---------------------------------------------------------------------------
__global__ void __launch_bounds__(256) embed_gemm(
    const int*   __restrict__ idx,
    const float* __restrict__ emb,
    const float* __restrict__ Wih_f, const float* __restrict__ bih_f, const float* __restrict__ bhh_f,
    const float* __restrict__ Wih_b, const float* __restrict__ bih_b, const float* __restrict__ bhh_b)
{
    __shared__ __align__(16) float xsA[16 * DD * 2];
    const int tid = threadIdx.x;
    const int b0  = blockIdx.x * 32;
    const int t   = blockIdx.y;

    for (int i = tid; i < 32 * DD; i += 256) {
        int b = i / DD, k = i - b * DD;
        int id = idx[(b0 + b) * TT + t];
        xsA[(b >> 1) * (2 * DD) + k * 2 + (b & 1)] = emb[id * DD + k];
    }
    __syncthreads();

    #pragma unroll 1
    for (int g = 0; g < 4; ++g) {
        int col = tid + g * 256;
        int dir = col >> 9;
        int n   = col & 511;
        const float* W = dir ? Wih_b : Wih_f;
        float bias = dir ? (bih_b[n] + bhh_b[n]) : (bih_f[n] + bhh_f[n]);

        float w[DD];
        #pragma unroll
        for (int k = 0; k < DD; ++k) w[k] = W[n * DD + k];

        ull acc[16];
        ull bp2 = pack2(bias, bias);
        #pragma unroll
        for (int p = 0; p < 16; ++p) acc[p] = bp2;

        #pragma unroll 2
        for (int k = 0; k < DD; ++k) {
            ull w2 = pack2(w[k], w[k]);
            #pragma unroll
            for (int p = 0; p < 16; ++p) {
                ull x = *(const ull*)&xsA[p * (2 * DD) + k * 2];
                fma2(x, w2, acc[p]);
            }
        }

        float* dst = &g_xgT[dir][t][n][b0];
        #pragma unroll
        for (int p = 0; p < 16; ++p) {
            float a, b; unpack2(acc[p], a, b);
            *(float2*)&dst[2 * p] = make_float2(a, b);
        }
    }
}

// ---------------------------------------------------------------------------
// Persistent LSTM recurrence (R11 design + narrowing register-permuted reduce).
// grid (4 kq, 32 bt, 2 dir) = 256 CTAs x 256 threads, cluster (4,1,1), 2 CTA/SM.
// Thread: kk = warp*4 + (lane&3), kgrp = lane>>2 -> 16-k input slice;
// owns all 4 gates x 8 batches over its slice (64 w regs, 16 ull accs).
//
// Accumulator permutation: A[g][q] holds batch-pair p = q ^ (kgrp>>1).
// h sections store pairs in q-order (q = pair ^ (s>>1) within section s), so
// the MAC loop reads A-order directly. Reduction narrows each round:
//   r1 (xor16): A[g][q] += shfl(A[g][q^2]), q=0,1   (16 SHFL + 8 add2)
//   r2 (xor 8): A[g][0] += shfl(A[g][1])            ( 8 SHFL + 4 add2)
//   r3 (xor 4): A[g][0] += shfl(A[g][0])            ( 8 SHFL + 4 add2)
// After r3, A[g][0] = full sum for this lane's (kk, batch-pair); pick hie half.
// ---------------------------------------------------------------------------
#define SEC_W  132                 // words per 16-k section (16*8 + 4 pad)
#define HB_W   (8 * SEC_W)         // 1056 words per buffer

__global__ void __launch_bounds__(256, 2) __cluster_dims__(4, 1, 1)
lstm_rw2(const float* __restrict__ Whh_f, const float* __restrict__ Whh_b,
         const float* __restrict__ masks, float* __restrict__ out)
{
    __shared__ __align__(16) float hb[2][HB_W];

    const int tid  = threadIdx.x;
    const int kq   = blockIdx.x;             // k-quarter == cluster rank
    const int bt   = blockIdx.y;
    const int d    = blockIdx.z;
    const int K0   = kq * 32;
    const int bb0  = bt * 8;
    const int lane = tid & 31;
    const int warp = tid >> 5;

    const int kkl   = lane & 3;
    const int kgrp  = lane >> 2;             // 0..7 (lane bits 2..4 -> xor 4,8,16)
    const int kk    = warp * 4 + kkl;        // 0..31
    const int kglob = K0 + kk;
    const int bu    = bb0 + kgrp;            // owned batch

    const float* Whh = d ? Whh_b : Whh_f;

    // ---- weights: 4 gate rows x own 16-k slice, in registers ----
    float w[4][16];
    #pragma unroll
    for (int g = 0; g < 4; ++g) {
        const float4* src = (const float4*)&Whh[(g * 128 + kglob) * 128 + kgrp * 16];
        #pragma unroll
        for (int q = 0; q < 4; ++q) {
            float4 v = src[q];
            w[g][4 * q + 0] = v.x; w[g][4 * q + 1] = v.y;
            w[g][4 * q + 2] = v.z; w[g][4 * q + 3] = v.w;
        }
    }

    // zero h buffer 0
    for (int i = tid; i < HB_W; i += 256) hb[0][i] = 0.f;

    // ---- h store word (q-permuted) + peer push addresses ----
    // section s = kglob>>4; pair slot q = (kgrp>>1) ^ (s>>1); hie = kgrp&1
    const int hs  = kglob >> 4;
    const int hq  = ((kgrp >> 1) ^ (hs >> 1)) & 3;
    const int hw  = hs * SEC_W + (kglob & 15) * 8 + hq * 2 + (kgrp & 1);
    float* loc0 = &hb[0][hw];
    const unsigned par_off = (unsigned)(HB_W * 4);   // hb[1] - hb[0] bytes
    unsigned rem0[3];
    {
        unsigned a0 = smem_u32(&hb[0][0]) + (unsigned)(hw * 4);
        #pragma unroll
        for (int p = 0; p < 3; ++p) {
            unsigned pr = (kq + 1 + p) & 3;
            asm("mapa.shared::cluster.u32 %0, %1, %2;" : "=r"(rem0[p]) : "r"(a0), "r"(pr));
        }
    }

    // ---- per-thread state ----
    float c = 0.f, m = -3.0e38f;

    const int tstep = d ? -1 : 1;
    int t = d ? (TT - 1) : 0;

    // prefetch xg (4 gate rows, own batch) + mask penalty for step 0
    float xn0, xn1, xn2, xn3, pen;
    {
        const float* p = &g_xgT[d][t][0][bu];
        xn0 = __ldg(p + (0 * 128 + kglob) * BB);
        xn1 = __ldg(p + (1 * 128 + kglob) * BB);
        xn2 = __ldg(p + (2 * 128 + kglob) * BB);
        xn3 = __ldg(p + (3 * 128 + kglob) * BB);
        pen = (1.0f - __ldg(&masks[bu * TT + t])) * 1e8f;
    }

    __syncthreads();   // hb[0] zeroed (local); peers independent

    const int hie = kgrp & 1;

    int cur = 0;
    for (int s = 0; s < TT; ++s) {
        float cx0 = xn0, cx1 = xn1, cx2 = xn2, cx3 = xn3, cpen = pen;
        // prefetch next step (hides under MAC loop)
        {
            int t2 = t + tstep;
            t2 = (t2 < 0) ? 0 : (t2 > TT - 1 ? TT - 1 : t2);
            const float* p = &g_xgT[d][t2][0][bu];
            xn0 = __ldg(p + (0 * 128 + kglob) * BB);
            xn1 = __ldg(p + (1 * 128 + kglob) * BB);
            xn2 = __ldg(p + (2 * 128 + kglob) * BB);
            xn3 = __ldg(p + (3 * 128 + kglob) * BB);
            pen = (1.0f - __ldg(&masks[bu * TT + t2])) * 1e8f;
        }

        // ---- MAC: own 16-k slice, 4 gates x 4 q-slots (q-permuted pairs) ----
        ull A[4][4];
        #pragma unroll
        for (int g = 0; g < 4; ++g)
            #pragma unroll
            for (int q = 0; q < 4; ++q) A[g][q] = 0ull;

        const float* hc = &hb[cur][kgrp * SEC_W];
        #pragma unroll
        for (int i = 0; i < 16; ++i) {
            ulonglong2 hA = *(const ulonglong2*)(hc + i * 8);      // q=0, q=1
            ulonglong2 hB = *(const ulonglong2*)(hc + i * 8 + 4);  // q=2, q=3
            #pragma unroll
            for (int g = 0; g < 4; ++g) {
                ull w2 = pack2(w[g][i], w[g][i]);
                fma2(hA.x, w2, A[g][0]);
                fma2(hA.y, w2, A[g][1]);
                fma2(hB.x, w2, A[g][2]);
                fma2(hB.y, w2, A[g][3]);
            }
        }

        // ---- narrowing butterfly over 8 kgrps (32 SHFL + 16 add2) ----
        #pragma unroll
        for (int g = 0; g < 4; ++g) {
            A[g][0] = add2(A[g][0], __shfl_xor_sync(0xffffffffu, A[g][2], 16));
            A[g][1] = add2(A[g][1], __shfl_xor_sync(0xffffffffu, A[g][3], 16));
        }
        #pragma unroll
        for (int g = 0; g < 4; ++g)
            A[g][0] = add2(A[g][0], __shfl_xor_sync(0xffffffffu, A[g][1], 8));
        #pragma unroll
        for (int g = 0; g < 4; ++g)
            A[g][0] = add2(A[g][0], __shfl_xor_sync(0xffffffffu, A[g][0], 4));

        // ---- update: lane owns (kglob, bu); pick hie half of A[g][0] ----
        float aa, bb2, gi, gf, gg, go;
        unpack2(A[0][0], aa, bb2); gi = hie ? bb2 : aa;
        unpack2(A[1][0], aa, bb2); gf = hie ? bb2 : aa;
        unpack2(A[2][0], aa, bb2); gg = hie ? bb2 : aa;
        unpack2(A[3][0], aa, bb2); go = hie ? bb2 : aa;
        gi += cx0; gf += cx1; gg += cx2; go += cx3;

        c = sigf(gf) * c + sigf(gi) * tanhf_(gg);
        float hv = sigf(go) * tanhf_(c);
        m = fmaxf(m, hv - cpen);

        if (s < TT - 1) {
            // write next h buffer: local + 3 DSMEM peers (4B each)
            unsigned nb = cur ? 0u : par_off;
            *(float*)((char*)loc0 + nb) = hv;
            asm volatile("st.shared::cluster.f32 [%0], %1;" :: "r"(rem0[0] + nb), "f"(hv) : "memory");
            asm volatile("st.shared::cluster.f32 [%0], %1;" :: "r"(rem0[1] + nb), "f"(hv) : "memory");
            asm volatile("st.shared::cluster.f32 [%0], %1;" :: "r"(rem0[2] + nb), "f"(hv) : "memory");
            // split cluster barrier: orders pushes + hb reuse, syncs CTAs
            asm volatile("barrier.cluster.arrive.aligned;" ::: "memory");
            asm volatile("barrier.cluster.wait.aligned;"   ::: "memory");
        }

        cur ^= 1;
        t += tstep;
    }

    out[bu * HID + d * HH + kglob] = m;
}

// ---------------------------------------------------------------------------
extern "C" void kernel_launch(void* const* d_in, const int* in_sizes, int n_in,
                              void* d_out, int out_size)
{
    (void)in_sizes; (void)n_in; (void)out_size;
    const int*   idx   = (const int*)  d_in[0];
    const float* masks = (const float*)d_in[1];
    const float* emb   = (const float*)d_in[2];
    const float* Wih_f = (const float*)d_in[3];
    const float* Whh_f = (const float*)d_in[4];
    const float* bih_f = (const float*)d_in[5];
    const float* bhh_f = (const float*)d_in[6];
    const float* Wih_b = (const float*)d_in[7];
    const float* Whh_b = (const float*)d_in[8];
    const float* bih_b = (const float*)d_in[9];
    const float* bhh_b = (const float*)d_in[10];
    float* out = (float*)d_out;

    embed_gemm<<<dim3(8, TT), 256>>>(idx, emb, Wih_f, bih_f, bhh_f,
                                     Wih_b, bih_b, bhh_b);
    lstm_rw2<<<dim3(4, 32, 2), 256>>>(Whh_f, Whh_b, masks, out);
}